// round 15
// baseline (speedup 1.0000x reference)
#include <cuda_runtime.h>
#include <cuda_bf16.h>

#define NBAT 1024
#define TT   128
#define RS   480           // slot stride in floats (256 Q + 212 payload + pad)
#define NSLOT 6            // slot consumed at iter t rewritten at t+2 -> race-free post-f2 reads
#define SLOTB (RS * 4)

__device__ __forceinline__ float dot12(const float4* a, const float4* b) {
    float4 a0 = a[0], a1 = a[1], a2 = a[2];
    float4 b0 = b[0], b1 = b[1], b2 = b[2];
    return a0.x*b0.x + a0.y*b0.y + a0.z*b0.z + a0.w*b0.w
         + a1.x*b1.x + a1.y*b1.y + a1.z*b1.z + a1.w*b1.w
         + a2.x*b2.x + a2.y*b2.y + a2.z*b2.z + a2.w*b2.w;
}

// dot of a held float4-triple against a shared row
__device__ __forceinline__ float dot12h(float4 h0, float4 h1, float4 h2, const float4* b) {
    float4 b0 = b[0], b1 = b[1], b2 = b[2];
    return h0.x*b0.x + h0.y*b0.y + h0.z*b0.z + h0.w*b0.w
         + h1.x*b1.x + h1.y*b1.y + h1.z*b1.z + h1.w*b1.w
         + h2.x*b2.x + h2.y*b2.y + h2.z*b2.z + h2.w*b2.w;
}

__device__ __forceinline__ void cpa4(unsigned s, const float* g) {
    asm volatile("cp.async.ca.shared.global [%0], [%1], 4;" :: "r"(s), "l"(g));
}
__device__ __forceinline__ void cpa16(unsigned s, const float* g) {
    asm volatile("cp.async.cg.shared.global [%0], [%1], 16;" :: "r"(s), "l"(g));
}
__device__ __forceinline__ void cpa_commit() { asm volatile("cp.async.commit_group;"); }
__device__ __forceinline__ void cpa_wait4()  { asm volatile("cp.async.wait_group 4;" ::: "memory"); }

__global__ __launch_bounds__(256, 7) void lqr_kernel(
    const float* __restrict__ x_init,     // [NB, 12]
    const float* __restrict__ current_u,  // [NB, T, 4]
    const float* __restrict__ Qg,         // [NB, T, 16, 16]
    const float* __restrict__ pg,         // [NB, T, 16]
    const float* __restrict__ Ag,         // [NB, T, 12, 12]
    const float* __restrict__ Bg,         // [NB, T, 12, 4]
    float* __restrict__ out)              // [xs | us | cost]
{
    const int b   = blockIdx.x;
    const int tid = threadIdx.x;
    const size_t bT = (size_t)b * TT;

    // Slot layout (floats): [0..255] Q row-major
    //   bwd: [256..447] FT (16 rows x 12, FT[j][k] = F[k][j])
    //   fwd: [256..399] A row-major, [400..447] B row-major
    //   [448..463] p ; [464..467] cu (fwd)
    __shared__ __align__(16) float ring[NSLOT * RS];
    __shared__ __align__(16) float sV[12 * 12];
    __shared__ __align__(16) float sv[12];
    __shared__ __align__(16) float sMT[16 * 12];
    __shared__ __align__(16) float sQt[256];
    __shared__ __align__(16) float sqt[16];
    __shared__ __align__(16) float sKt[4 * 12];
    __shared__ __align__(16) float skt[4];
    __shared__ __align__(16) float sk_all[TT * 4];
    __shared__ __align__(16) float sxu[16];
    __shared__ __align__(16) float sxn[12];

    const unsigned ring_u32 = (unsigned)__cvta_generic_to_shared(ring);

    if (tid < 144) sV[tid] = 0.f;
    if (tid < 12)  sv[tid] = 0.f;

    // ---- per-thread bwd copy jobs (destination offsets loop-invariant) ----
    unsigned xdoff = 0; int xstr = 0;
    {
        if (tid < 144) { int k = tid / 12, j = tid - 12 * k; xdoff = (256u + j * 12 + k) * 4u; xstr = 144; }
        else if (tid < 192) { int idx = tid - 144, k = idx >> 2, c = idx & 3;
                              xdoff = (256u + (12 + c) * 12 + k) * 4u; xstr = 48; }
        else if (tid < 196) { int idx = tid - 192; xdoff = (448u + idx * 4) * 4u; xstr = 16; }
    }

    // ---- bwd prologue: fill slots 0..3 with steps T-1..T-4 ----
    #pragma unroll
    for (int d = 0; d < 4; ++d) {
        const size_t bt = bT + (TT - 1 - d);
        const unsigned fb = ring_u32 + (unsigned)(d * SLOTB);
        if (tid < 64)  cpa16(fb + tid * 16u, Qg + bt * 256 + tid * 4);
        if (tid < 144)      cpa4(fb + xdoff, Ag + bt * 144 + tid);
        else if (tid < 192) cpa4(fb + xdoff, Bg + bt * 48 + (tid - 144));
        else if (tid < 196) cpa16(fb + xdoff, pg + bt * 16 + (tid - 192) * 4);
        cpa_commit();
    }

    // main-loop src pointers start at step T-5
    const float* qsrc = Qg + (bT + TT - 5) * 256 + tid * 4;
    const float* xsrc = nullptr;
    if (tid < 144)      xsrc = Ag + (bT + TT - 5) * 144 + tid;
    else if (tid < 192) xsrc = Bg + (bT + TT - 5) * 48 + (tid - 144);
    else if (tid < 196) xsrc = pg + (bT + TT - 5) * 16 + (tid - 192) * 4;

    int use_f = 0;  // slot base in floats; fill slot = use + 4 (mod NSLOT)

    // ================= BACKWARD SCAN =================
    for (int t = TT - 1; t >= 0; --t) {
        const float* sl = ring + use_f;

        // refill (step t-4) into slot (use+4)%NSLOT, issued before the wait
        {
            int fill_f = use_f + 4 * RS; if (fill_f >= NSLOT * RS) fill_f -= NSLOT * RS;
            const unsigned fb = ring_u32 + (unsigned)fill_f * 4u;
            if (t >= 4) {
                if (tid < 64)  cpa16(fb + tid * 16u, qsrc);
                if (tid < 192)      { if (xsrc) cpa4(fb + xdoff, xsrc); }
                else if (tid < 196) cpa16(fb + xdoff, xsrc);
                qsrc -= 256; xsrc -= xstr;
            }
            cpa_commit();
        }
        cpa_wait4();
        __syncthreads();   // s1: slot t visible; prev sV/sv (warp 0) visible

        // phase 2 (48 threads, 4 outputs/thread holding the FT row):
        //   MT[j][i0+3r] = dot(V row (i0+3r), FT row j) ; i0 = tid>>4 in 0..2, j = tid&15
        if (tid < 48) {
            int i0 = tid >> 4, j = tid & 15;
            const float4* ftj = (const float4*)&sl[256 + j * 12];
            float4 h0 = ftj[0], h1 = ftj[1], h2 = ftj[2];   // held once
            float* mout = &sMT[j * 12 + i0];
            mout[0] = dot12h(h0, h1, h2, (const float4*)&sV[i0 * 12]);
            mout[3] = dot12h(h0, h1, h2, (const float4*)&sV[(i0 + 3) * 12]);
            mout[6] = dot12h(h0, h1, h2, (const float4*)&sV[(i0 + 6) * 12]);
            mout[9] = dot12h(h0, h1, h2, (const float4*)&sV[(i0 + 9) * 12]);
        } else if (tid < 64) {
            // qt = p + FT v
            int j = tid - 48;
            sqt[j] = sl[448 + j] + dot12((const float4*)&sl[256 + j * 12], (const float4*)sv);
        }
        __syncthreads();  // s2

        // phase 3 (64 threads, 4 outputs/thread holding the sMT row):
        //   Qt[i0+4r][j] = Q0 + dot(FT row (i0+4r), MT row j) ; i0 = tid>>4 in 0..3, j = tid&15
        if (tid < 64) {
            int i0 = tid >> 4, j = tid & 15;
            const float4* mtj = (const float4*)&sMT[j * 12];
            float4 h0 = mtj[0], h1 = mtj[1], h2 = mtj[2];   // held once
            #pragma unroll
            for (int r = 0; r < 4; ++r) {
                int i = i0 + 4 * r;
                sQt[i * 16 + j] = sl[i * 16 + j]
                                + dot12h(h0, h1, h2, (const float4*)&sl[256 + i * 12]);
            }
        }
        __syncthreads();  // s3

        // ---- phases 4+5 fused on WARP 0 only (no block barrier) ----
        if (tid < 32) {
            const int lane = tid;
            const int m = lane & 15;
            const int ca = m & 3;        // cofactor column
            const int cb = m >> 2;       // cofactor row

            // Quu rows (broadcast loads)
            float q[4][4];
            #pragma unroll
            for (int r = 0; r < 4; ++r) {
                float4 qr = *(const float4*)&sQt[(12 + r) * 16 + 12];
                q[r][0] = qr.x; q[r][1] = qr.y; q[r][2] = qr.z; q[r][3] = qr.w;
            }
            // signed cofactor C_{cb,ca}: one per lane (mirrored on 16..31)
            int r0 = (cb == 0) ? 1 : 0, r1 = (cb <= 1) ? 2 : 1, r2 = (cb <= 2) ? 3 : 2;
            int c0 = (ca == 0) ? 1 : 0, c1 = (ca <= 1) ? 2 : 1, c2 = (ca <= 2) ? 3 : 2;
            float C = q[r0][c0] * (q[r1][c1] * q[r2][c2] - q[r1][c2] * q[r2][c1])
                    - q[r0][c1] * (q[r1][c0] * q[r2][c2] - q[r1][c2] * q[r2][c0])
                    + q[r0][c2] * (q[r1][c0] * q[r2][c1] - q[r1][c1] * q[r2][c0]);
            float w = ((ca + cb) & 1) ? -C : C;

            // det via column-ca expansion, reduce over cofactor-row groups
            float pd = q[cb][ca] * w;
            pd += __shfl_xor_sync(0xffffffffu, pd, 4);
            pd += __shfl_xor_sync(0xffffffffu, pd, 8);
            float ninvd = -1.0f / pd;

            // job A: all 32 lanes -> Kt[a][j], a = lane>>3, j = lane&7
            {
                int a = lane >> 3, j = lane & 7;
                float w0 = __shfl_sync(0xffffffffu, w, a);
                float w1 = __shfl_sync(0xffffffffu, w, a + 4);
                float w2 = __shfl_sync(0xffffffffu, w, a + 8);
                float w3 = __shfl_sync(0xffffffffu, w, a + 12);
                float nv = __shfl_sync(0xffffffffu, ninvd, a);
                float s = w0 * sQt[12 * 16 + j] + w1 * sQt[13 * 16 + j]
                        + w2 * sQt[14 * 16 + j] + w3 * sQt[15 * 16 + j];
                sKt[a * 12 + j] = nv * s;
            }
            // job B: lanes 0..15 -> Kt[a][8+(lane&3)], a = (lane>>2)&3
            {
                int a = (lane >> 2) & 3, j = 8 + (lane & 3);
                float w0 = __shfl_sync(0xffffffffu, w, a);
                float w1 = __shfl_sync(0xffffffffu, w, a + 4);
                float w2 = __shfl_sync(0xffffffffu, w, a + 8);
                float w3 = __shfl_sync(0xffffffffu, w, a + 12);
                float nv = __shfl_sync(0xffffffffu, ninvd, a);
                float s = w0 * sQt[12 * 16 + j] + w1 * sQt[13 * 16 + j]
                        + w2 * sQt[14 * 16 + j] + w3 * sQt[15 * 16 + j];
                if (lane < 16) sKt[a * 12 + j] = nv * s;
            }
            // kt: lanes 16..19 -> kt[a], a = lane-16
            {
                int a = (lane - 16) & 3;
                float w0 = __shfl_sync(0xffffffffu, w, a);
                float w1 = __shfl_sync(0xffffffffu, w, a + 4);
                float w2 = __shfl_sync(0xffffffffu, w, a + 8);
                float w3 = __shfl_sync(0xffffffffu, w, a + 12);
                float nv = __shfl_sync(0xffffffffu, ninvd, a);
                float s = w0 * sqt[12] + w1 * sqt[13] + w2 * sqt[14] + w3 * sqt[15];
                if (lane >= 16 && lane < 20) {
                    float kk = nv * s;
                    skt[a] = kk;
                    sk_all[t * 4 + a] = kk;
                }
            }
            __syncwarp();  // Kt/skt visible within warp 0

            // phase 5: Vn = Qxx + Qxu Kt ; vn = qx + Qxu kt
            #pragma unroll
            for (int pass = 0; pass < 2; ++pass) {
                int e = lane + pass * 32;
                if (e < 36) {
                    int i = e / 3, jq = e - (e / 3) * 3;
                    float4 acc = *(const float4*)&sQt[i * 16 + jq * 4];
                    float4 qxu = *(const float4*)&sQt[i * 16 + 12];
                    float4 k0 = *(const float4*)&sKt[0 * 12 + jq * 4];
                    float4 k1 = *(const float4*)&sKt[1 * 12 + jq * 4];
                    float4 k2 = *(const float4*)&sKt[2 * 12 + jq * 4];
                    float4 k3 = *(const float4*)&sKt[3 * 12 + jq * 4];
                    acc.x += qxu.x * k0.x + qxu.y * k1.x + qxu.z * k2.x + qxu.w * k3.x;
                    acc.y += qxu.x * k0.y + qxu.y * k1.y + qxu.z * k2.y + qxu.w * k3.y;
                    acc.z += qxu.x * k0.z + qxu.y * k1.z + qxu.z * k2.z + qxu.w * k3.z;
                    acc.w += qxu.x * k0.w + qxu.y * k1.w + qxu.z * k2.w + qxu.w * k3.w;
                    *(float4*)&sV[i * 12 + jq * 4] = acc;
                }
            }
            // v: lanes 4..15 -> rows 0..11
            if (lane >= 4 && lane < 16) {
                int i = lane - 4;
                sv[i] = sqt[i] + sQt[i * 16 + 12] * skt[0] + sQt[i * 16 + 13] * skt[1]
                               + sQt[i * 16 + 14] * skt[2] + sQt[i * 16 + 15] * skt[3];
            }
        }
        use_f += RS; if (use_f >= NSLOT * RS) use_f = 0;
        // next-iter s1 orders warp 0's sV/sv/sKt writes before their readers
    }

    // ================= FORWARD SCAN =================
    float cost = 0.f;
    if (tid < 12) sxn[tid] = x_init[b * 12 + tid];

    // fwd copy jobs: all float4
    unsigned fdoff = 0; int fstr = 0; const float* fsrc = nullptr;
    {
        const size_t bt = bT + 4;  // first refill step
        if (tid < 64)       { fdoff = tid * 16u;                     fsrc = Qg + bt * 256 + tid * 4;          fstr = 256; }
        else if (tid < 100) { int i = tid - 64;  fdoff = (256u + i * 4) * 4u; fsrc = Ag + bt * 144 + i * 4;   fstr = 144; }
        else if (tid < 112) { int i = tid - 100; fdoff = (400u + i * 4) * 4u; fsrc = Bg + bt * 48 + i * 4;    fstr = 48;  }
        else if (tid < 116) { int i = tid - 112; fdoff = (448u + i * 4) * 4u; fsrc = pg + bt * 16 + i * 4;    fstr = 16;  }
        else if (tid == 116){ fdoff = 464u * 4u;                     fsrc = current_u + bt * 4;               fstr = 4;   }
    }

    // fwd prologue: steps 0..3 into slots 0..3
    #pragma unroll
    for (int d = 0; d < 4; ++d) {
        const size_t bt = bT + d;
        const unsigned fb = ring_u32 + (unsigned)(d * SLOTB);
        if (tid < 64)       cpa16(fb + tid * 16u, Qg + bt * 256 + tid * 4);
        else if (tid < 100) cpa16(fb + fdoff, Ag + bt * 144 + (tid - 64) * 4);
        else if (tid < 112) cpa16(fb + fdoff, Bg + bt * 48 + (tid - 100) * 4);
        else if (tid < 116) cpa16(fb + fdoff, pg + bt * 16 + (tid - 112) * 4);
        else if (tid == 116) cpa16(fb + fdoff, current_u + bt * 4);
        cpa_commit();
    }

    float* out_xs   = out;
    float* out_us   = out + (size_t)NBAT * TT * 12;
    float* out_cost = out_us + (size_t)NBAT * TT * 4;

    use_f = 0;
    for (int t = 0; t < TT; ++t) {
        const float* sl = ring + use_f;

        {
            int fill_f = use_f + 4 * RS; if (fill_f >= NSLOT * RS) fill_f -= NSLOT * RS;
            const unsigned fb = ring_u32 + (unsigned)fill_f * 4u;
            if (t + 4 < TT) {
                if (fsrc) cpa16(fb + fdoff, fsrc);
                fsrc += fstr;
            }
            cpa_commit();
        }
        cpa_wait4();
        __syncthreads();  // f1: slot visible; prev-iter sxn visible

        if (tid < 12) {
            float xv = sxn[tid];
            sxu[tid] = xv;
            out_xs[(bT + t) * 12 + tid] = xv;
        } else if (tid < 16) {
            int a = tid - 12;
            float u = sl[464 + a] + sk_all[t * 4 + a];
            sxu[tid] = u;
            out_us[(bT + t) * 4 + a] = u;
        }
        __syncthreads();  // f2

        // cost: 16 threads (warp 0), one full Q row each; in-warp reduce.
        // Post-f2 sl reads safe: NSLOT=6 => slot rewritten at t+2's top, ordered by f1/f2 of t+1.
        if (tid < 16) {
            const float4* Qr = (const float4*)&sl[tid * 16];
            float4 q0 = Qr[0], q1 = Qr[1], q2 = Qr[2], q3 = Qr[3];
            const float4* X = (const float4*)sxu;
            float4 x0 = X[0], x1 = X[1], x2 = X[2], x3 = X[3];
            float y = q0.x*x0.x + q0.y*x0.y + q0.z*x0.z + q0.w*x0.w
                    + q1.x*x1.x + q1.y*x1.y + q1.z*x1.z + q1.w*x1.w
                    + q2.x*x2.x + q2.y*x2.y + q2.z*x2.z + q2.w*x2.w
                    + q3.x*x3.x + q3.y*x3.y + q3.z*x3.z + q3.w*x3.w;
            float c = sxu[tid] * (0.5f * y + sl[448 + tid]);
            c += __shfl_down_sync(0x0000ffffu, c, 8);
            c += __shfl_down_sync(0x0000ffffu, c, 4);
            c += __shfl_down_sync(0x0000ffffu, c, 2);
            c += __shfl_down_sync(0x0000ffffu, c, 1);
            if (tid == 0) cost += c;
        }
        // dynamics: xnext = A x + B u (warp 2; next-iter f1 orders sxn)
        if (tid >= 64 && tid < 76) {
            int i = tid - 64;
            const float4* Ar = (const float4*)&sl[256 + i * 12];
            float4 a0 = Ar[0], a1 = Ar[1], a2 = Ar[2];
            float4 b0 = *(const float4*)&sl[400 + i * 4];
            const float4* X = (const float4*)sxu;
            float4 x0 = X[0], x1 = X[1], x2 = X[2], x3 = X[3];
            float s = a0.x*x0.x + a0.y*x0.y + a0.z*x0.z + a0.w*x0.w
                    + a1.x*x1.x + a1.y*x1.y + a1.z*x1.z + a1.w*x1.w
                    + a2.x*x2.x + a2.y*x2.y + a2.z*x2.z + a2.w*x2.w
                    + b0.x*x3.x + b0.y*x3.y + b0.z*x3.z + b0.w*x3.w;
            sxn[i] = s;
        }
        use_f += RS; if (use_f >= NSLOT * RS) use_f = 0;
    }

    if (tid == 0) out_cost[b] = cost;
}

extern "C" void kernel_launch(void* const* d_in, const int* in_sizes, int n_in,
                              void* d_out, int out_size) {
    // metadata order: x_init, current_x(unused), current_u, Q, p, A, Bmat, time(unused)
    const float* x_init    = (const float*)d_in[0];
    const float* current_u = (const float*)d_in[2];
    const float* Q         = (const float*)d_in[3];
    const float* p         = (const float*)d_in[4];
    const float* A         = (const float*)d_in[5];
    const float* Bmat      = (const float*)d_in[6];
    float* out = (float*)d_out;

    lqr_kernel<<<NBAT, 256>>>(x_init, current_u, Q, p, A, Bmat, out);
}

// round 17
// speedup vs baseline: 1.2996x; 1.2996x over previous
#include <cuda_runtime.h>
#include <cuda_bf16.h>

#define NBAT 1024
#define TT   128
#define RS   480           // slot stride in floats (256 Q + 212 payload + pad)
#define NSLOT 6            // slot consumed at iter t rewritten at t+2 -> race-free
#define SLOTB (RS * 4)

#define BARC() asm volatile("bar.sync 1, 128;" ::: "memory")  // consumer warps 0-3

__device__ __forceinline__ float dot12(const float4* a, const float4* b) {
    float4 a0 = a[0], a1 = a[1], a2 = a[2];
    float4 b0 = b[0], b1 = b[1], b2 = b[2];
    return a0.x*b0.x + a0.y*b0.y + a0.z*b0.z + a0.w*b0.w
         + a1.x*b1.x + a1.y*b1.y + a1.z*b1.z + a1.w*b1.w
         + a2.x*b2.x + a2.y*b2.y + a2.z*b2.z + a2.w*b2.w;
}

__device__ __forceinline__ void cpa4(unsigned s, const float* g) {
    asm volatile("cp.async.ca.shared.global [%0], [%1], 4;" :: "r"(s), "l"(g));
}
__device__ __forceinline__ void cpa16(unsigned s, const float* g) {
    asm volatile("cp.async.cg.shared.global [%0], [%1], 16;" :: "r"(s), "l"(g));
}
__device__ __forceinline__ void cpa_commit() { asm volatile("cp.async.commit_group;"); }
__device__ __forceinline__ void cpa_wait4()  { asm volatile("cp.async.wait_group 4;" ::: "memory"); }

__global__ __launch_bounds__(256, 7) void lqr_kernel(
    const float* __restrict__ x_init,     // [NB, 12]
    const float* __restrict__ current_u,  // [NB, T, 4]
    const float* __restrict__ Qg,         // [NB, T, 16, 16]
    const float* __restrict__ pg,         // [NB, T, 16]
    const float* __restrict__ Ag,         // [NB, T, 12, 12]
    const float* __restrict__ Bg,         // [NB, T, 12, 4]
    float* __restrict__ out)              // [xs | us | cost]
{
    const int b    = blockIdx.x;
    const int tid  = threadIdx.x;
    const int ptid = tid - 128;           // producer index (valid for tid >= 128)
    const size_t bT = (size_t)b * TT;

    // Slot layout (floats): [0..255] Q row-major
    //   bwd: [256..447] FT (16 rows x 12, FT[j][k] = F[k][j])
    //   fwd: [256..399] A row-major, [400..447] B row-major
    //   [448..463] p ; [464..467] cu (fwd)
    __shared__ __align__(16) float ring[NSLOT * RS];
    __shared__ __align__(16) float sV[12 * 12];
    __shared__ __align__(16) float sv[12];
    __shared__ __align__(16) float sMT[16 * 12];
    __shared__ __align__(16) float sQt[256];
    __shared__ __align__(16) float sqt[16];
    __shared__ __align__(16) float sKt[4 * 12];
    __shared__ __align__(16) float skt[4];
    __shared__ __align__(16) float sk_all[TT * 4];
    __shared__ __align__(16) float sxu[16];
    __shared__ __align__(16) float sxn[12];

    const unsigned ring_u32 = (unsigned)__cvta_generic_to_shared(ring);

    if (tid < 144) sV[tid] = 0.f;
    if (tid < 12)  sv[tid] = 0.f;

    // ---- producer (tid>=128) bwd copy-job descriptors ----
    unsigned doffA1 = 0, doff2 = 0, doffp = 0;
    const float *qsrc = Qg, *a1src = Ag, *s2src = Ag, *psrc = pg;
    int str2 = 0;
    if (tid >= 128) {
        { int r = ptid / 12, c = ptid - 12 * r; doffA1 = (256u + c * 12 + r) * 4u; }
        if (ptid < 16) {
            int a2 = 128 + ptid, r = a2 / 12, c = a2 - 12 * r;
            doff2 = (256u + c * 12 + r) * 4u; str2 = 144;
        } else if (ptid < 64) {
            int bi = ptid - 16, k = bi >> 2, c = bi & 3;
            doff2 = (256u + (12 + c) * 12 + k) * 4u; str2 = 48;
        } else if (ptid < 68) {
            doffp = (448u + (ptid - 64) * 4) * 4u;
        }
        // ---- bwd prologue: slots 0..3 = steps T-1..T-4 ----
        #pragma unroll
        for (int d = 0; d < 4; ++d) {
            const size_t bt = bT + (TT - 1 - d);
            const unsigned fb = ring_u32 + (unsigned)(d * SLOTB);
            if (ptid < 64) cpa16(fb + (unsigned)ptid * 16u, Qg + bt * 256 + ptid * 4);
            cpa4(fb + doffA1, Ag + bt * 144 + ptid);
            if (ptid < 16)      cpa4(fb + doff2, Ag + bt * 144 + 128 + ptid);
            else if (ptid < 64) cpa4(fb + doff2, Bg + bt * 48 + (ptid - 16));
            else if (ptid < 68) cpa16(fb + doffp, pg + bt * 16 + (ptid - 64) * 4);
            cpa_commit();
        }
        // main-loop src pointers start at step T-5
        const size_t bt0 = bT + TT - 5;
        qsrc  = Qg + bt0 * 256 + ptid * 4;
        a1src = Ag + bt0 * 144 + ptid;
        if (ptid < 16)      s2src = Ag + bt0 * 144 + 128 + ptid;
        else if (ptid < 64) s2src = Bg + bt0 * 48 + (ptid - 16);
        psrc  = pg + bt0 * 16 + ((ptid - 64) & 3) * 4;
    }

    int use_f = 0;  // slot base in floats; fill slot = use + 4 (mod NSLOT)

    // ================= BACKWARD SCAN =================
    for (int t = TT - 1; t >= 0; --t) {
        if (tid >= 128) {
            int fill_f = use_f + 4 * RS; if (fill_f >= NSLOT * RS) fill_f -= NSLOT * RS;
            const unsigned fb = ring_u32 + (unsigned)fill_f * 4u;
            if (t >= 4) {
                if (ptid < 64) cpa16(fb + (unsigned)ptid * 16u, qsrc);
                cpa4(fb + doffA1, a1src);
                if (ptid < 64)      cpa4(fb + doff2, s2src);
                else if (ptid < 68) cpa16(fb + doffp, psrc);
                qsrc -= 256; a1src -= 144; s2src -= str2; psrc -= 16;
            }
            cpa_commit();
            cpa_wait4();   // slot t's group retired on producer threads
        }
        __syncthreads();   // s1: slot t visible block-wide; prev sV/sv visible

        const float* sl = ring + use_f;
        if (tid < 128) {
            // phase 2 (3 warps, 2 outputs/thread sharing the FT-row fetch)
            if (tid < 96) {
                int i0 = tid >> 4, j = tid & 15;
                const float4* ftj = (const float4*)&sl[256 + j * 12];
                float m0 = dot12((const float4*)&sV[i0 * 12],      ftj);
                float m1 = dot12((const float4*)&sV[(i0 + 6) * 12], ftj);
                sMT[j * 12 + i0]     = m0;
                sMT[j * 12 + i0 + 6] = m1;
            } else if (tid < 112) {
                int j = tid - 96;
                sqt[j] = sl[448 + j] + dot12((const float4*)&sl[256 + j * 12], (const float4*)sv);
            }
            BARC();  // s2 (consumers only)

            // phase 3 (4 warps, 2 outputs/thread sharing the sMT-row fetch)
            {
                int i0 = tid >> 4, j = tid & 15;
                const float4* mtj = (const float4*)&sMT[j * 12];
                float q0 = sl[i0 * 16 + j]       + dot12((const float4*)&sl[256 + i0 * 12],       mtj);
                float q1 = sl[(i0 + 8) * 16 + j] + dot12((const float4*)&sl[256 + (i0 + 8) * 12], mtj);
                sQt[i0 * 16 + j]       = q0;
                sQt[(i0 + 8) * 16 + j] = q1;
            }
            BARC();  // s3 (consumers only)

            // ---- phases 4+5 fused on WARP 0 ----
            if (tid < 32) {
                const int lane = tid;
                const int m = lane & 15;
                const int ca = m & 3, cb = m >> 2;

                float q[4][4];
                #pragma unroll
                for (int r = 0; r < 4; ++r) {
                    float4 qr = *(const float4*)&sQt[(12 + r) * 16 + 12];
                    q[r][0] = qr.x; q[r][1] = qr.y; q[r][2] = qr.z; q[r][3] = qr.w;
                }
                int r0 = (cb == 0) ? 1 : 0, r1 = (cb <= 1) ? 2 : 1, r2 = (cb <= 2) ? 3 : 2;
                int c0 = (ca == 0) ? 1 : 0, c1 = (ca <= 1) ? 2 : 1, c2 = (ca <= 2) ? 3 : 2;
                float C = q[r0][c0] * (q[r1][c1] * q[r2][c2] - q[r1][c2] * q[r2][c1])
                        - q[r0][c1] * (q[r1][c0] * q[r2][c2] - q[r1][c2] * q[r2][c0])
                        + q[r0][c2] * (q[r1][c0] * q[r2][c1] - q[r1][c1] * q[r2][c0]);
                float w = ((ca + cb) & 1) ? -C : C;

                float pd = q[cb][ca] * w;
                pd += __shfl_xor_sync(0xffffffffu, pd, 4);
                pd += __shfl_xor_sync(0xffffffffu, pd, 8);
                float ninvd = -1.0f / pd;

                {   // Kt[a][j], a = lane>>3, j = lane&7
                    int a = lane >> 3, j = lane & 7;
                    float w0 = __shfl_sync(0xffffffffu, w, a);
                    float w1 = __shfl_sync(0xffffffffu, w, a + 4);
                    float w2 = __shfl_sync(0xffffffffu, w, a + 8);
                    float w3 = __shfl_sync(0xffffffffu, w, a + 12);
                    float nv = __shfl_sync(0xffffffffu, ninvd, a);
                    float s = w0 * sQt[12 * 16 + j] + w1 * sQt[13 * 16 + j]
                            + w2 * sQt[14 * 16 + j] + w3 * sQt[15 * 16 + j];
                    sKt[a * 12 + j] = nv * s;
                }
                {   // Kt[a][8+(lane&3)], a = (lane>>2)&3  (lanes 0..15)
                    int a = (lane >> 2) & 3, j = 8 + (lane & 3);
                    float w0 = __shfl_sync(0xffffffffu, w, a);
                    float w1 = __shfl_sync(0xffffffffu, w, a + 4);
                    float w2 = __shfl_sync(0xffffffffu, w, a + 8);
                    float w3 = __shfl_sync(0xffffffffu, w, a + 12);
                    float nv = __shfl_sync(0xffffffffu, ninvd, a);
                    float s = w0 * sQt[12 * 16 + j] + w1 * sQt[13 * 16 + j]
                            + w2 * sQt[14 * 16 + j] + w3 * sQt[15 * 16 + j];
                    if (lane < 16) sKt[a * 12 + j] = nv * s;
                }
                {   // kt[a] (lanes 16..19)
                    int a = (lane - 16) & 3;
                    float w0 = __shfl_sync(0xffffffffu, w, a);
                    float w1 = __shfl_sync(0xffffffffu, w, a + 4);
                    float w2 = __shfl_sync(0xffffffffu, w, a + 8);
                    float w3 = __shfl_sync(0xffffffffu, w, a + 12);
                    float nv = __shfl_sync(0xffffffffu, ninvd, a);
                    float s = w0 * sqt[12] + w1 * sqt[13] + w2 * sqt[14] + w3 * sqt[15];
                    if (lane >= 16 && lane < 20) {
                        float kk = nv * s;
                        skt[a] = kk;
                        sk_all[t * 4 + a] = kk;
                    }
                }
                __syncwarp();

                // phase 5: Vn = Qxx + Qxu Kt ; vn = qx + Qxu kt
                #pragma unroll
                for (int pass = 0; pass < 2; ++pass) {
                    int e = lane + pass * 32;
                    if (e < 36) {
                        int i = e / 3, jq = e - (e / 3) * 3;
                        float4 acc = *(const float4*)&sQt[i * 16 + jq * 4];
                        float4 qxu = *(const float4*)&sQt[i * 16 + 12];
                        float4 k0 = *(const float4*)&sKt[0 * 12 + jq * 4];
                        float4 k1 = *(const float4*)&sKt[1 * 12 + jq * 4];
                        float4 k2 = *(const float4*)&sKt[2 * 12 + jq * 4];
                        float4 k3 = *(const float4*)&sKt[3 * 12 + jq * 4];
                        acc.x += qxu.x * k0.x + qxu.y * k1.x + qxu.z * k2.x + qxu.w * k3.x;
                        acc.y += qxu.x * k0.y + qxu.y * k1.y + qxu.z * k2.y + qxu.w * k3.y;
                        acc.z += qxu.x * k0.z + qxu.y * k1.z + qxu.z * k2.z + qxu.w * k3.z;
                        acc.w += qxu.x * k0.w + qxu.y * k1.w + qxu.z * k2.w + qxu.w * k3.w;
                        *(float4*)&sV[i * 12 + jq * 4] = acc;
                    }
                }
                if (lane >= 4 && lane < 16) {
                    int i = lane - 4;
                    sv[i] = sqt[i] + sQt[i * 16 + 12] * skt[0] + sQt[i * 16 + 13] * skt[1]
                                   + sQt[i * 16 + 14] * skt[2] + sQt[i * 16 + 15] * skt[3];
                }
            }
        }
        use_f += RS; if (use_f >= NSLOT * RS) use_f = 0;
        // next-iter s1 orders warp 0's sV/sv/sKt writes before readers
    }

    // RACE FIX (R15 bug): producers must not overwrite ring slots 0..3 with the
    // fwd prologue until consumers finish their last backward reads (slot of
    // bwd t=0, which IS in 0..3). One full barrier closes the hole.
    __syncthreads();

    // ================= FORWARD SCAN =================
    float cost = 0.f;
    if (tid < 12) sxn[tid] = x_init[b * 12 + tid];

    // producer fwd jobs: all cpa16, 1/thread (ptid < 117)
    unsigned fdoff = 0; int fstr = 0; const float* fsrc = Qg;
    if (tid >= 128) {
        const size_t bt = bT + 4;  // first refill step
        if (ptid < 64)       { fdoff = (unsigned)ptid * 16u;            fsrc = Qg + bt * 256 + ptid * 4;          fstr = 256; }
        else if (ptid < 100) { int i = ptid - 64;  fdoff = (256u + i * 4) * 4u; fsrc = Ag + bt * 144 + i * 4;     fstr = 144; }
        else if (ptid < 112) { int i = ptid - 100; fdoff = (400u + i * 4) * 4u; fsrc = Bg + bt * 48 + i * 4;      fstr = 48;  }
        else if (ptid < 116) { int i = ptid - 112; fdoff = (448u + i * 4) * 4u; fsrc = pg + bt * 16 + i * 4;      fstr = 16;  }
        else if (ptid == 116){ fdoff = 464u * 4u;                       fsrc = current_u + bt * 4;                fstr = 4;   }
        // fwd prologue: steps 0..3 into slots 0..3
        #pragma unroll
        for (int d = 0; d < 4; ++d) {
            const size_t bd = bT + d;
            const unsigned fb = ring_u32 + (unsigned)(d * SLOTB);
            if (ptid < 64)       cpa16(fb + (unsigned)ptid * 16u, Qg + bd * 256 + ptid * 4);
            else if (ptid < 100) cpa16(fb + fdoff, Ag + bd * 144 + (ptid - 64) * 4);
            else if (ptid < 112) cpa16(fb + fdoff, Bg + bd * 48 + (ptid - 100) * 4);
            else if (ptid < 116) cpa16(fb + fdoff, pg + bd * 16 + (ptid - 112) * 4);
            else if (ptid == 116) cpa16(fb + fdoff, current_u + bd * 4);
            cpa_commit();
        }
    }

    float* out_xs   = out;
    float* out_us   = out + (size_t)NBAT * TT * 12;
    float* out_cost = out_us + (size_t)NBAT * TT * 4;

    use_f = 0;
    for (int t = 0; t < TT; ++t) {
        if (tid >= 128) {
            int fill_f = use_f + 4 * RS; if (fill_f >= NSLOT * RS) fill_f -= NSLOT * RS;
            const unsigned fb = ring_u32 + (unsigned)fill_f * 4u;
            if (t + 4 < TT) {
                if (ptid < 117) cpa16(fb + fdoff, fsrc);
                fsrc += fstr;
            }
            cpa_commit();
            cpa_wait4();
        }
        __syncthreads();  // f1: slot visible; prev-iter sxn/sk_all visible

        const float* sl = ring + use_f;
        if (tid < 128) {
            if (tid < 12) {
                float xv = sxn[tid];
                sxu[tid] = xv;
                out_xs[(bT + t) * 12 + tid] = xv;
            } else if (tid < 16) {
                int a = tid - 12;
                float u = sl[464 + a] + sk_all[t * 4 + a];
                sxu[tid] = u;
                out_us[(bT + t) * 4 + a] = u;
            }
            BARC();  // f2 (consumers only)

            // cost: 16 threads (warp 0); post-f2 sl reads safe (NSLOT=6: slot
            // rewritten by producers only after f1(t+1), which follows these reads)
            if (tid < 16) {
                const float4* Qr = (const float4*)&sl[tid * 16];
                float4 q0 = Qr[0], q1 = Qr[1], q2 = Qr[2], q3 = Qr[3];
                const float4* X = (const float4*)sxu;
                float4 x0 = X[0], x1 = X[1], x2 = X[2], x3 = X[3];
                float y = q0.x*x0.x + q0.y*x0.y + q0.z*x0.z + q0.w*x0.w
                        + q1.x*x1.x + q1.y*x1.y + q1.z*x1.z + q1.w*x1.w
                        + q2.x*x2.x + q2.y*x2.y + q2.z*x2.z + q2.w*x2.w
                        + q3.x*x3.x + q3.y*x3.y + q3.z*x3.z + q3.w*x3.w;
                float c = sxu[tid] * (0.5f * y + sl[448 + tid]);
                c += __shfl_down_sync(0x0000ffffu, c, 8);
                c += __shfl_down_sync(0x0000ffffu, c, 4);
                c += __shfl_down_sync(0x0000ffffu, c, 2);
                c += __shfl_down_sync(0x0000ffffu, c, 1);
                if (tid == 0) cost += c;
            }
            // dynamics: xnext = A x + B u (warp 2)
            if (tid >= 64 && tid < 76) {
                int i = tid - 64;
                const float4* Ar = (const float4*)&sl[256 + i * 12];
                float4 a0 = Ar[0], a1 = Ar[1], a2 = Ar[2];
                float4 b0 = *(const float4*)&sl[400 + i * 4];
                const float4* X = (const float4*)sxu;
                float4 x0 = X[0], x1 = X[1], x2 = X[2], x3 = X[3];
                float s = a0.x*x0.x + a0.y*x0.y + a0.z*x0.z + a0.w*x0.w
                        + a1.x*x1.x + a1.y*x1.y + a1.z*x1.z + a1.w*x1.w
                        + a2.x*x2.x + a2.y*x2.y + a2.z*x2.z + a2.w*x2.w
                        + b0.x*x3.x + b0.y*x3.y + b0.z*x3.z + b0.w*x3.w;
                sxn[i] = s;
            }
        }
        use_f += RS; if (use_f >= NSLOT * RS) use_f = 0;
    }

    if (tid == 0) out_cost[b] = cost;
}

extern "C" void kernel_launch(void* const* d_in, const int* in_sizes, int n_in,
                              void* d_out, int out_size) {
    // metadata order: x_init, current_x(unused), current_u, Q, p, A, Bmat, time(unused)
    const float* x_init    = (const float*)d_in[0];
    const float* current_u = (const float*)d_in[2];
    const float* Q         = (const float*)d_in[3];
    const float* p         = (const float*)d_in[4];
    const float* A         = (const float*)d_in[5];
    const float* Bmat      = (const float*)d_in[6];
    float* out = (float*)d_out;

    lqr_kernel<<<NBAT, 256>>>(x_init, current_u, Q, p, A, Bmat, out);
}